// round 5
// baseline (speedup 1.0000x reference)
#include <cuda_runtime.h>
#include <math.h>

#define EMBED 256
#define BATCH 32
#define TQ 1024
#define TKV 512
#define NMELS_R 320
#define NLAYERS 4
#define SQRT_HALF 0.70710678118654752440f

// ---------------- scratch (device globals; no allocation allowed) ----------------
__device__ float g_h   [BATCH * TQ * EMBED];   // main hidden state
__device__ float g_h2  [BATCH * TQ * EMBED];   // fc ping-pong / qout
__device__ float g_ctx [BATCH * TQ * EMBED];   // attention context
__device__ float g_kout[BATCH * TKV * EMBED];
__device__ float g_vout[BATCH * TKV * EMBED];
__device__ float g_big [BATCH * TQ * 512];     // conv output (B,T,512) / attention scores (B,1024,512)
__device__ float g_peq [TQ * EMBED];
__device__ float g_pek [TKV * EMBED];

// ---------------- positional encoding ----------------
// XLA rewrites division-by-constant into multiplication-by-reciprocal (documented
// numerics difference). After the pow subgraph constant-folds, the reference angle
// is effectively: angle = pos * ((pos*rate) * (1/power)), all f32.
// pow/sin/cos are evaluated via double (== correctly-rounded f32 == glibc/HloEvaluator).
__global__ void posenc_kernel(float* __restrict__ pe, int T, float rate) {
    int idx = blockIdx.x * blockDim.x + threadIdx.x;
    if (idx >= T * EMBED) return;
    int t = idx / EMBED;
    int c = idx - t * EMBED;
    double e = (double)(2.0f * (float)(c >> 1) / 256.0f);   // exact in fp32
    float power = (float)pow(10000.0, e);                   // correctly-rounded f32
    float recip = 1.0f / power;                             // f32 reciprocal (XLA div->mul rewrite)
    float p  = (float)t;
    float t1 = p * rate;          // exact (rate = 1.0 or 2.0)
    float t2 = t1 * recip;        // multiply by reciprocal, NOT divide
    float angle = p * t2;
    double a = (double)angle;
    pe[idx] = (c & 1) ? (float)cos(a) : (float)sin(a);
}

// ---------------- generic SGEMM (exact fp32) ----------------
enum AMode { A_NORMAL = 0, A_ADDPE = 1, A_CONV = 2 };
enum Epi   { E_RELU = 0, E_BIAS = 1, E_NONE = 2, E_SCALE = 3, E_RESID = 4 };

// C[M,N] = epi( A[M,K] @ B[K,N] ), TRANSB: B stored [N,K]
// A_ADDPE: A += pe[(row % pe_period), k]   (requires K == 256)
// A_CONV : A row r -> (b = r>>10, t = r&1023); k = tap*256+ci gathers
//          h[b, t-(4-tap)*dil, ci] (zero for t-shift<0). K must be 1280.
template<int AMODE, bool TRANSB, int EPI>
__global__ void __launch_bounds__(256, 2)
gemm_kernel(const float* __restrict__ A, const float* __restrict__ Bm,
            float* __restrict__ C,
            const float* __restrict__ bias,
            const float* __restrict__ resid,
            const float* __restrict__ pe, int pe_period,
            int M, int N, int K,
            long long sA, long long sB, long long sC,
            int dil, float scale)
{
    __shared__ float As[8][132];
    __shared__ float Bs[8][132];

    const int bz = blockIdx.z;
    A  += bz * sA;
    Bm += bz * sB;
    C  += bz * sC;

    const int row0 = blockIdx.y * 128;
    const int col0 = blockIdx.x * 128;
    const int tid  = threadIdx.x;

    const int a_r  = tid >> 1;
    const int a_k4 = (tid & 1) * 4;
    const int b_k  = tid >> 5;
    const int b_n4 = (tid & 31) * 4;

    const int tx = tid & 15;
    const int ty = tid >> 4;

    float acc[8][8];
#pragma unroll
    for (int i = 0; i < 8; i++)
#pragma unroll
        for (int j = 0; j < 8; j++) acc[i][j] = 0.0f;

    for (int k0 = 0; k0 < K; k0 += 8) {
        // ---- load A tile ----
        {
            const int gr = row0 + a_r;
            float4 v = make_float4(0.f, 0.f, 0.f, 0.f);
            if (AMODE == A_CONV) {
                const int kg   = k0 + a_k4;
                const int tap  = kg >> 8;       // 256 channels per tap, tile never straddles
                const int ci   = kg & 255;
                const int shift = (4 - tap) * dil;
                const int b_ = gr >> 10;
                const int t_ = gr & 1023;
                if (t_ >= shift)
                    v = *(const float4*)&A[((long long)((b_ << 10) + (t_ - shift))) * EMBED + ci];
            } else {
                if (gr < M) {
                    v = *(const float4*)&A[(long long)gr * K + k0 + a_k4];
                    if (AMODE == A_ADDPE) {
                        const float4 p4 = *(const float4*)&pe[(long long)(gr % pe_period) * EMBED + k0 + a_k4];
                        v.x += p4.x; v.y += p4.y; v.z += p4.z; v.w += p4.w;
                    }
                }
            }
            As[a_k4 + 0][a_r] = v.x;
            As[a_k4 + 1][a_r] = v.y;
            As[a_k4 + 2][a_r] = v.z;
            As[a_k4 + 3][a_r] = v.w;
        }
        // ---- load B tile ----
        if (!TRANSB) {
            const int gk = k0 + b_k;
            const int gn = col0 + b_n4;
            float4 v = make_float4(0.f, 0.f, 0.f, 0.f);
            if (gn < N)
                v = *(const float4*)&Bm[(long long)gk * N + gn];
            Bs[b_k][b_n4 + 0] = v.x;
            Bs[b_k][b_n4 + 1] = v.y;
            Bs[b_k][b_n4 + 2] = v.z;
            Bs[b_k][b_n4 + 3] = v.w;
        } else {
            const int gn = col0 + a_r;  // B stored [N,K]
            float4 v = make_float4(0.f, 0.f, 0.f, 0.f);
            if (gn < N)
                v = *(const float4*)&Bm[(long long)gn * K + k0 + a_k4];
            Bs[a_k4 + 0][a_r] = v.x;
            Bs[a_k4 + 1][a_r] = v.y;
            Bs[a_k4 + 2][a_r] = v.z;
            Bs[a_k4 + 3][a_r] = v.w;
        }
        __syncthreads();

#pragma unroll
        for (int kk = 0; kk < 8; kk++) {
            float ra[8], rb[8];
#pragma unroll
            for (int i = 0; i < 8; i++) ra[i] = As[kk][ty * 8 + i];
#pragma unroll
            for (int j = 0; j < 8; j++) rb[j] = Bs[kk][tx * 8 + j];
#pragma unroll
            for (int i = 0; i < 8; i++)
#pragma unroll
                for (int j = 0; j < 8; j++)
                    acc[i][j] = fmaf(ra[i], rb[j], acc[i][j]);
        }
        __syncthreads();
    }

    // ---- epilogue ----
#pragma unroll
    for (int i = 0; i < 8; i++) {
        const int r = row0 + ty * 8 + i;
        if (r >= M) continue;
#pragma unroll
        for (int j = 0; j < 8; j++) {
            const int cc = col0 + tx * 8 + j;
            if (cc >= N) continue;
            float val = acc[i][j];
            if (EPI == E_RELU)  val = fmaxf(val + bias[cc], 0.0f);
            if (EPI == E_BIAS)  val = val + bias[cc];
            if (EPI == E_SCALE) val = val * scale;
            if (EPI == E_RESID) val = (val + bias[cc] + resid[(long long)r * N + cc]) * SQRT_HALF;
            C[(long long)r * N + cc] = val;
        }
    }
}

// ---------------- GLU + residual: h = (h + a * sigmoid(g)) * sqrt(0.5) ----------------
__global__ void glu_kernel(const float* __restrict__ y, float* __restrict__ h) {
    long long idx = (long long)blockIdx.x * blockDim.x + threadIdx.x;
    if (idx >= (long long)BATCH * TQ * EMBED) return;
    long long r = idx >> 8;
    int c = (int)(idx & 255);
    float a = y[r * 512 + c];
    float g = y[r * 512 + 256 + c];
    float s = 1.0f / (1.0f + expf(-g));
    h[idx] = (h[idx] + a * s) * SQRT_HALF;
}

// ---------------- row softmax over 512 ----------------
__global__ void softmax_kernel(float* __restrict__ x) {
    __shared__ float red[128];
    float* p = x + (long long)blockIdx.x * 512;
    const int tid = threadIdx.x;
    float v[4];
    float m = -1e30f;
#pragma unroll
    for (int i = 0; i < 4; i++) { v[i] = p[tid + i * 128]; m = fmaxf(m, v[i]); }
    red[tid] = m; __syncthreads();
#pragma unroll
    for (int s = 64; s > 0; s >>= 1) {
        if (tid < s) red[tid] = fmaxf(red[tid], red[tid + s]);
        __syncthreads();
    }
    m = red[0];
    __syncthreads();
    float sum = 0.0f;
#pragma unroll
    for (int i = 0; i < 4; i++) { v[i] = expf(v[i] - m); sum += v[i]; }
    red[tid] = sum; __syncthreads();
#pragma unroll
    for (int s = 64; s > 0; s >>= 1) {
        if (tid < s) red[tid] += red[tid + s];
        __syncthreads();
    }
    float inv = 1.0f / red[0];
#pragma unroll
    for (int i = 0; i < 4; i++) p[tid + i * 128] = v[i] * inv;
}

// ---------------- done head: sigmoid(h @ w_done + b_done), N=2 ----------------
__global__ void done_kernel(const float* __restrict__ h, const float* __restrict__ w,
                            const float* __restrict__ b, float* __restrict__ out) {
    const int row  = blockIdx.x * 8 + (threadIdx.x >> 5);
    const int lane = threadIdx.x & 31;
    if (row >= BATCH * TQ) return;
    const float* hr = h + (long long)row * EMBED;
    float s0 = 0.0f, s1 = 0.0f;
    for (int k = lane; k < EMBED; k += 32) {
        float hv = hr[k];
        s0 = fmaf(hv, w[k * 2 + 0], s0);
        s1 = fmaf(hv, w[k * 2 + 1], s1);
    }
#pragma unroll
    for (int o = 16; o > 0; o >>= 1) {
        s0 += __shfl_down_sync(0xffffffffu, s0, o);
        s1 += __shfl_down_sync(0xffffffffu, s1, o);
    }
    if (lane == 0) {
        out[row * 2 + 0] = 1.0f / (1.0f + expf(-(s0 + b[0])));
        out[row * 2 + 1] = 1.0f / (1.0f + expf(-(s1 + b[1])));
    }
}

// ---------------- host orchestration ----------------
static inline dim3 gemm_grid(int M, int N, int z) {
    return dim3((N + 127) / 128, (M + 127) / 128, z);
}

extern "C" void kernel_launch(void* const* d_in, const int* in_sizes, int n_in,
                              void* d_out, int out_size) {
    const float* inputs  = (const float*)d_in[0];
    const float* keys    = (const float*)d_in[1];
    const float* values  = (const float*)d_in[2];
    const float* w_first = (const float*)d_in[3];
    const float* b_first = (const float*)d_in[4];
    const float* fc_w    = (const float*)d_in[5];
    const float* fc_b    = (const float*)d_in[6];
    const float* conv_w  = (const float*)d_in[7];
    const float* conv_b  = (const float*)d_in[8];
    const float* att_w1  = (const float*)d_in[9];
    const float* att_b1  = (const float*)d_in[10];
    const float* att_w2  = (const float*)d_in[11];
    const float* att_b2  = (const float*)d_in[12];
    const float* att_w3  = (const float*)d_in[13];
    const float* att_b3  = (const float*)d_in[14];
    const float* att_wo  = (const float*)d_in[15];
    const float* att_bo  = (const float*)d_in[16];
    const float* w_done  = (const float*)d_in[17];
    const float* b_done  = (const float*)d_in[18];
    const float* w_mel   = (const float*)d_in[19];
    const float* b_mel   = (const float*)d_in[20];

    float* out      = (float*)d_out;
    float* out_mel  = out;
    float* out_done = out + (long long)BATCH * TQ * NMELS_R;
    float* out_h    = out_done + (long long)BATCH * TQ * 2;

    float *h, *h2, *ctx, *kout, *vout, *big, *peq, *pek;
    cudaGetSymbolAddress((void**)&h,    g_h);
    cudaGetSymbolAddress((void**)&h2,   g_h2);
    cudaGetSymbolAddress((void**)&ctx,  g_ctx);
    cudaGetSymbolAddress((void**)&kout, g_kout);
    cudaGetSymbolAddress((void**)&vout, g_vout);
    cudaGetSymbolAddress((void**)&big,  g_big);
    cudaGetSymbolAddress((void**)&peq,  g_peq);
    cudaGetSymbolAddress((void**)&pek,  g_pek);

    const int M  = BATCH * TQ;    // 32768
    const int Mk = BATCH * TKV;   // 16384
    const float rsqrt_tk = 1.0f / sqrtf((float)TKV);

    posenc_kernel<<<(TQ * EMBED + 255) / 256, 256>>>(peq, TQ, 1.0f);
    posenc_kernel<<<(TKV * EMBED + 255) / 256, 256>>>(pek, TKV, 2.0f);

    // h2 = relu(inputs @ w_first + b_first)
    gemm_kernel<A_NORMAL, false, E_RELU><<<gemm_grid(M, EMBED, 1), 256>>>(
        inputs, w_first, h2, b_first, nullptr, nullptr, 0,
        M, EMBED, NMELS_R, 0, 0, 0, 0, 0.0f);
    // fc0: h2 -> h ; fc1: h -> h2 ; fc2: h2 -> h
    gemm_kernel<A_NORMAL, false, E_RELU><<<gemm_grid(M, EMBED, 1), 256>>>(
        h2, fc_w + 0 * EMBED * EMBED, h, fc_b + 0 * EMBED, nullptr, nullptr, 0,
        M, EMBED, EMBED, 0, 0, 0, 0, 0.0f);
    gemm_kernel<A_NORMAL, false, E_RELU><<<gemm_grid(M, EMBED, 1), 256>>>(
        h, fc_w + 1 * EMBED * EMBED, h2, fc_b + 1 * EMBED, nullptr, nullptr, 0,
        M, EMBED, EMBED, 0, 0, 0, 0, 0.0f);
    gemm_kernel<A_NORMAL, false, E_RELU><<<gemm_grid(M, EMBED, 1), 256>>>(
        h2, fc_w + 2 * EMBED * EMBED, h, fc_b + 2 * EMBED, nullptr, nullptr, 0,
        M, EMBED, EMBED, 0, 0, 0, 0, 0.0f);

    for (int i = 0; i < NLAYERS; i++) {
        const int dil = 1 << i;
        // conv (im2col gather GEMM): big[M,512] = conv(h) + bias
        gemm_kernel<A_CONV, false, E_BIAS><<<gemm_grid(M, 512, 1), 256>>>(
            h, conv_w + (long long)i * 5 * EMBED * 512, big,
            conv_b + i * 512, nullptr, nullptr, 0,
            M, 512, 5 * EMBED, 0, 0, 0, dil, 0.0f);
        // GLU + residual into h
        glu_kernel<<<(M * EMBED + 255) / 256, 256>>>(big, h);

        // q/k/v projections
        gemm_kernel<A_ADDPE, false, E_BIAS><<<gemm_grid(M, EMBED, 1), 256>>>(
            h, att_w2 + (long long)i * EMBED * EMBED, h2,
            att_b2 + i * EMBED, nullptr, peq, TQ,
            M, EMBED, EMBED, 0, 0, 0, 0, 0.0f);
        gemm_kernel<A_ADDPE, false, E_BIAS><<<gemm_grid(Mk, EMBED, 1), 256>>>(
            keys, att_w1 + (long long)i * EMBED * EMBED, kout,
            att_b1 + i * EMBED, nullptr, pek, TKV,
            Mk, EMBED, EMBED, 0, 0, 0, 0, 0.0f);
        gemm_kernel<A_NORMAL, false, E_BIAS><<<gemm_grid(Mk, EMBED, 1), 256>>>(
            values, att_w3 + (long long)i * EMBED * EMBED, vout,
            att_b3 + i * EMBED, nullptr, nullptr, 0,
            Mk, EMBED, EMBED, 0, 0, 0, 0, 0.0f);

        // scores[b] = qout[b] @ kout[b]^T   (batched, TRANSB)
        gemm_kernel<A_NORMAL, true, E_NONE><<<gemm_grid(TQ, TKV, BATCH), 256>>>(
            h2, kout, big, nullptr, nullptr, nullptr, 0,
            TQ, TKV, EMBED,
            (long long)TQ * EMBED, (long long)TKV * EMBED, (long long)TQ * TKV,
            0, 0.0f);
        // softmax over keys
        softmax_kernel<<<M, 128>>>(big);
        // ctx[b] = softmax @ vout[b] * rsqrt(TK)
        gemm_kernel<A_NORMAL, false, E_SCALE><<<gemm_grid(TQ, EMBED, BATCH), 256>>>(
            big, vout, ctx, nullptr, nullptr, nullptr, 0,
            TQ, EMBED, TKV,
            (long long)TQ * TKV, (long long)TKV * EMBED, (long long)TQ * EMBED,
            0, rsqrt_tk);
        // h = (ctx @ wo + bo + h) * sqrt(0.5)
        gemm_kernel<A_NORMAL, false, E_RESID><<<gemm_grid(M, EMBED, 1), 256>>>(
            ctx, att_wo + (long long)i * EMBED * EMBED, h,
            att_bo + i * EMBED, h, nullptr, 0,
            M, EMBED, EMBED, 0, 0, 0, 0, 0.0f);
    }

    // mel head
    gemm_kernel<A_NORMAL, false, E_BIAS><<<gemm_grid(M, NMELS_R, 1), 256>>>(
        h, w_mel, out_mel, b_mel, nullptr, nullptr, 0,
        M, NMELS_R, EMBED, 0, 0, 0, 0, 0.0f);
    // done head
    done_kernel<<<(M + 7) / 8, 256>>>(h, w_done, b_done, out_done);
    // h output
    cudaMemcpyAsync(out_h, h, sizeof(float) * (size_t)M * EMBED,
                    cudaMemcpyDeviceToDevice);
}

// round 6
// speedup vs baseline: 1.1703x; 1.1703x over previous
#include <cuda_runtime.h>
#include <math.h>
#include <stdint.h>

#define EMBED 256
#define BATCH 32
#define TQ 1024
#define TKV 512
#define NMELS_R 320
#define NLAYERS 4
#define SQRT_HALF 0.70710678118654752440f
#define KTILE 16

// ---------------- scratch (device globals; no allocation allowed) ----------------
__device__ float g_h   [BATCH * TQ * EMBED];   // main hidden state
__device__ float g_h2  [BATCH * TQ * EMBED];   // qout / fc ping-pong
__device__ float g_ctx [BATCH * TQ * EMBED];   // attention context
__device__ float g_qin [BATCH * TQ * EMBED];   // h + peq (query input)
__device__ float g_kin [BATCH * TKV * EMBED];  // keys + pek (layer-invariant)
__device__ float g_kout[BATCH * TKV * EMBED];
__device__ float g_vout[BATCH * TKV * EMBED];
__device__ float g_big [BATCH * TQ * 512];     // conv output / attention scores
__device__ float g_peq [TQ * EMBED];
__device__ float g_pek [TKV * EMBED];

// ---------------- cp.async helpers ----------------
__device__ __forceinline__ uint32_t smem_u32(const void* p) {
    return (uint32_t)__cvta_generic_to_shared(p);
}
__device__ __forceinline__ void cp_async16(uint32_t dst, const void* src, int src_bytes) {
    asm volatile("cp.async.cg.shared.global [%0], [%1], 16, %2;\n"
                 :: "r"(dst), "l"(src), "r"(src_bytes));
}
__device__ __forceinline__ void cp_async_commit() {
    asm volatile("cp.async.commit_group;\n");
}
__device__ __forceinline__ void cp_async_wait0() {
    asm volatile("cp.async.wait_group 0;\n");
}

// ---------------- positional encoding ----------------
// VERIFIED numerics (R5 pass @5.5e-7): angle = pos * ((pos*rate) * (1/power)),
// all f32 (XLA rewrites div-by-const to mul-by-reciprocal); pow/sin/cos via double
// (correctly-rounded f32, fast-math-immune). DO NOT CHANGE.
__global__ void posenc_kernel(float* __restrict__ pe, int T, float rate) {
    int idx = blockIdx.x * blockDim.x + threadIdx.x;
    if (idx >= T * EMBED) return;
    int t = idx / EMBED;
    int c = idx - t * EMBED;
    double e = (double)(2.0f * (float)(c >> 1) / 256.0f);
    float power = (float)pow(10000.0, e);
    float recip = 1.0f / power;
    float p  = (float)t;
    float t1 = p * rate;
    float t2 = t1 * recip;
    float angle = p * t2;
    double a = (double)angle;
    pe[idx] = (c & 1) ? (float)cos(a) : (float)sin(a);
}

// ---------------- kin = keys + pek (computed once; layer-invariant) ----------------
__global__ void addpe_kernel(const float* __restrict__ x, const float* __restrict__ pe,
                             float* __restrict__ y, int period) {
    long long idx = (long long)blockIdx.x * blockDim.x + threadIdx.x;
    long long r = idx >> 8;
    int c = (int)(idx & 255);
    int t = (int)(r & (period - 1));
    y[idx] = x[idx] + pe[t * EMBED + c];
}

// ---------------- generic SGEMM, double-buffered cp.async pipeline ----------------
enum AMode { A_NORMAL = 0, A_CONV = 2 };
enum Epi   { E_RELU = 0, E_BIAS = 1, E_NONE = 2, E_SCALE = 3, E_RESID = 4 };

// C[M,N] = epi( A[M,K] @ B[K,N] );  TRANSB: B stored [N,K].
// A_CONV: row r -> (b=r>>10, t=r&1023); k = tap*256+ci gathers h[b, t-(4-tap)*dil, ci]
//         (zero when t<shift). K=1280; KTILE chunks never straddle a tap (256%16==0).
// Requirements: M%128==0, K%16==0, N%4==0 (N<128-multiple handled by guards).
template<int AMODE, bool TRANSB, int EPI>
__global__ void __launch_bounds__(256, 2)
gemm_kernel(const float* __restrict__ A, const float* __restrict__ Bm,
            float* __restrict__ C,
            const float* __restrict__ bias,
            const float* __restrict__ resid,
            int M, int N, int K,
            long long sA, long long sB, long long sC,
            int dil, float scale)
{
    __shared__ float As[2][128][KTILE];   // row-major (matches global contiguity)
    __shared__ float Bs[2][KTILE][128];   // k-major rows of N

    const int bz = blockIdx.z;
    A  += bz * sA;
    Bm += bz * sB;
    C  += bz * sC;

    const int row0 = blockIdx.y * 128;
    const int col0 = blockIdx.x * 128;
    const int tid  = threadIdx.x;
    const int tx = tid & 15;
    const int ty = tid >> 4;

    const int nk = K / KTILE;

    // ---- tile loaders ----
    // A: 128 rows x 16 k = 512 float4; thread handles idx = tid, tid+256
    auto load_A = [&](int kt, int b) {
#pragma unroll
        for (int u = 0; u < 2; u++) {
            const int idx = tid + u * 256;
            const int r  = idx >> 2;
            const int kc = (idx & 3) * 4;
            const int gr = row0 + r;
            const int kg = kt * KTILE + kc;
            const float* src;
            int sz = 16;
            if (AMODE == A_CONV) {
                const int tap = kg >> 8;
                const int ci  = kg & 255;
                const int shift = (4 - tap) * dil;
                const int b_ = gr >> 10;
                const int t_ = gr & 1023;
                if (t_ >= shift)
                    src = A + ((long long)((b_ << 10) + (t_ - shift))) * EMBED + ci;
                else { src = A; sz = 0; }
            } else {
                src = A + (long long)gr * K + kg;
            }
            cp_async16(smem_u32(&As[b][r][kc]), src, sz);
        }
    };
    // B (!TRANSB): 16 k x 128 n = 512 float4
    auto load_B = [&](int kt, int b) {
#pragma unroll
        for (int u = 0; u < 2; u++) {
            const int idx = tid + u * 256;
            const int kk = idx >> 5;
            const int nc = (idx & 31) * 4;
            const int gn = col0 + nc;
            const float* src = Bm + (long long)(kt * KTILE + kk) * N + gn;
            int sz = (gn < N) ? 16 : 0;
            if (gn >= N) src = Bm;
            cp_async16(smem_u32(&Bs[b][kk][nc]), src, sz);
        }
    };
    // TRANSB: B stored [N,K]; reg-stage + transpose into Bs
    float4 tb[2];
    auto ldg_Bt = [&](int kt) {
#pragma unroll
        for (int u = 0; u < 2; u++) {
            const int idx = tid + u * 256;
            const int n  = idx >> 2;
            const int kc = (idx & 3) * 4;
            const int gn = col0 + n;
            tb[u] = (gn < N) ? *(const float4*)&Bm[(long long)gn * K + kt * KTILE + kc]
                             : make_float4(0.f, 0.f, 0.f, 0.f);
        }
    };
    auto sts_Bt = [&](int b) {
#pragma unroll
        for (int u = 0; u < 2; u++) {
            const int idx = tid + u * 256;
            const int n  = idx >> 2;
            const int kc = (idx & 3) * 4;
            Bs[b][kc + 0][n] = tb[u].x;
            Bs[b][kc + 1][n] = tb[u].y;
            Bs[b][kc + 2][n] = tb[u].z;
            Bs[b][kc + 3][n] = tb[u].w;
        }
    };

    float acc[8][8];
#pragma unroll
    for (int i = 0; i < 8; i++)
#pragma unroll
        for (int j = 0; j < 8; j++) acc[i][j] = 0.0f;

    // ---- prologue: tile 0 into buffer 0 ----
    load_A(0, 0);
    if (!TRANSB) {
        load_B(0, 0);
        cp_async_commit();
        cp_async_wait0();
    } else {
        cp_async_commit();
        ldg_Bt(0);
        cp_async_wait0();
        sts_Bt(0);
    }
    __syncthreads();

    for (int t = 0; t < nk; t++) {
        const int cur = t & 1;
        const int nxt = cur ^ 1;
        const bool more = (t + 1 < nk);

        if (more) {
            load_A(t + 1, nxt);
            if (!TRANSB) load_B(t + 1, nxt);
            cp_async_commit();
            if (TRANSB) ldg_Bt(t + 1);
        }

        // ---- compute on cur ----
#pragma unroll
        for (int kk = 0; kk < KTILE; kk++) {
            float ra[8];
#pragma unroll
            for (int i = 0; i < 8; i++) ra[i] = As[cur][ty * 8 + i][kk];
            const float4 b0 = *(const float4*)&Bs[cur][kk][tx * 8];
            const float4 b1 = *(const float4*)&Bs[cur][kk][tx * 8 + 4];
            const float rb[8] = {b0.x, b0.y, b0.z, b0.w, b1.x, b1.y, b1.z, b1.w};
#pragma unroll
            for (int i = 0; i < 8; i++)
#pragma unroll
                for (int j = 0; j < 8; j++)
                    acc[i][j] = fmaf(ra[i], rb[j], acc[i][j]);
        }

        if (more && TRANSB) sts_Bt(nxt);
        cp_async_wait0();
        __syncthreads();
    }

    // ---- epilogue ----
#pragma unroll
    for (int i = 0; i < 8; i++) {
        const int r = row0 + ty * 8 + i;
#pragma unroll
        for (int j = 0; j < 8; j++) {
            const int cc = col0 + tx * 8 + j;
            if (cc >= N) continue;
            float val = acc[i][j];
            if (EPI == E_RELU)  val = fmaxf(val + bias[cc], 0.0f);
            if (EPI == E_BIAS)  val = val + bias[cc];
            if (EPI == E_SCALE) val = val * scale;
            if (EPI == E_RESID) val = (val + bias[cc] + resid[(long long)r * N + cc]) * SQRT_HALF;
            C[(long long)r * N + cc] = val;
        }
    }
}

// ---------------- GLU + residual + fused q-input ----------------
// h = (h + a*sigmoid(g))*sqrt(0.5);  qin = h + peq[t]
__global__ void glu_kernel(const float* __restrict__ y, float* __restrict__ h,
                           float* __restrict__ qin, const float* __restrict__ peq) {
    long long idx = (long long)blockIdx.x * blockDim.x + threadIdx.x;
    if (idx >= (long long)BATCH * TQ * EMBED) return;
    long long r = idx >> 8;
    int c = (int)(idx & 255);
    int t = (int)(r & 1023);
    float a = y[r * 512 + c];
    float g = y[r * 512 + 256 + c];
    float s = 1.0f / (1.0f + expf(-g));
    float hv = (h[idx] + a * s) * SQRT_HALF;
    h[idx] = hv;
    qin[idx] = hv + peq[t * EMBED + c];
}

// ---------------- row softmax over 512 ----------------
__global__ void softmax_kernel(float* __restrict__ x) {
    __shared__ float red[128];
    float* p = x + (long long)blockIdx.x * 512;
    const int tid = threadIdx.x;
    float v[4];
    float m = -1e30f;
#pragma unroll
    for (int i = 0; i < 4; i++) { v[i] = p[tid + i * 128]; m = fmaxf(m, v[i]); }
    red[tid] = m; __syncthreads();
#pragma unroll
    for (int s = 64; s > 0; s >>= 1) {
        if (tid < s) red[tid] = fmaxf(red[tid], red[tid + s]);
        __syncthreads();
    }
    m = red[0];
    __syncthreads();
    float sum = 0.0f;
#pragma unroll
    for (int i = 0; i < 4; i++) { v[i] = expf(v[i] - m); sum += v[i]; }
    red[tid] = sum; __syncthreads();
#pragma unroll
    for (int s = 64; s > 0; s >>= 1) {
        if (tid < s) red[tid] += red[tid + s];
        __syncthreads();
    }
    float inv = 1.0f / red[0];
#pragma unroll
    for (int i = 0; i < 4; i++) p[tid + i * 128] = v[i] * inv;
}

// ---------------- done head: sigmoid(h @ w_done + b_done), N=2 ----------------
__global__ void done_kernel(const float* __restrict__ h, const float* __restrict__ w,
                            const float* __restrict__ b, float* __restrict__ out) {
    const int row  = blockIdx.x * 8 + (threadIdx.x >> 5);
    const int lane = threadIdx.x & 31;
    if (row >= BATCH * TQ) return;
    const float* hr = h + (long long)row * EMBED;
    float s0 = 0.0f, s1 = 0.0f;
    for (int k = lane; k < EMBED; k += 32) {
        float hv = hr[k];
        s0 = fmaf(hv, w[k * 2 + 0], s0);
        s1 = fmaf(hv, w[k * 2 + 1], s1);
    }
#pragma unroll
    for (int o = 16; o > 0; o >>= 1) {
        s0 += __shfl_down_sync(0xffffffffu, s0, o);
        s1 += __shfl_down_sync(0xffffffffu, s1, o);
    }
    if (lane == 0) {
        out[row * 2 + 0] = 1.0f / (1.0f + expf(-(s0 + b[0])));
        out[row * 2 + 1] = 1.0f / (1.0f + expf(-(s1 + b[1])));
    }
}

// ---------------- host orchestration ----------------
static inline dim3 gemm_grid(int M, int N, int z) {
    return dim3((N + 127) / 128, (M + 127) / 128, z);
}

extern "C" void kernel_launch(void* const* d_in, const int* in_sizes, int n_in,
                              void* d_out, int out_size) {
    const float* inputs  = (const float*)d_in[0];
    const float* keys    = (const float*)d_in[1];
    const float* values  = (const float*)d_in[2];
    const float* w_first = (const float*)d_in[3];
    const float* b_first = (const float*)d_in[4];
    const float* fc_w    = (const float*)d_in[5];
    const float* fc_b    = (const float*)d_in[6];
    const float* conv_w  = (const float*)d_in[7];
    const float* conv_b  = (const float*)d_in[8];
    const float* att_w1  = (const float*)d_in[9];
    const float* att_b1  = (const float*)d_in[10];
    const float* att_w2  = (const float*)d_in[11];
    const float* att_b2  = (const float*)d_in[12];
    const float* att_w3  = (const float*)d_in[13];
    const float* att_b3  = (const float*)d_in[14];
    const float* att_wo  = (const float*)d_in[15];
    const float* att_bo  = (const float*)d_in[16];
    const float* w_done  = (const float*)d_in[17];
    const float* b_done  = (const float*)d_in[18];
    const float* w_mel   = (const float*)d_in[19];
    const float* b_mel   = (const float*)d_in[20];

    float* out      = (float*)d_out;
    float* out_mel  = out;
    float* out_done = out + (long long)BATCH * TQ * NMELS_R;
    float* out_h    = out_done + (long long)BATCH * TQ * 2;

    float *h, *h2, *ctx, *qin, *kin, *kout, *vout, *big, *peq, *pek;
    cudaGetSymbolAddress((void**)&h,    g_h);
    cudaGetSymbolAddress((void**)&h2,   g_h2);
    cudaGetSymbolAddress((void**)&ctx,  g_ctx);
    cudaGetSymbolAddress((void**)&qin,  g_qin);
    cudaGetSymbolAddress((void**)&kin,  g_kin);
    cudaGetSymbolAddress((void**)&kout, g_kout);
    cudaGetSymbolAddress((void**)&vout, g_vout);
    cudaGetSymbolAddress((void**)&big,  g_big);
    cudaGetSymbolAddress((void**)&peq,  g_peq);
    cudaGetSymbolAddress((void**)&pek,  g_pek);

    const int M  = BATCH * TQ;    // 32768
    const int Mk = BATCH * TKV;   // 16384
    const float rsqrt_tk = 1.0f / sqrtf((float)TKV);

    posenc_kernel<<<(TQ * EMBED + 255) / 256, 256>>>(peq, TQ, 1.0f);
    posenc_kernel<<<(TKV * EMBED + 255) / 256, 256>>>(pek, TKV, 2.0f);
    // kin = keys + pek (layer-invariant)
    addpe_kernel<<<(Mk * EMBED + 255) / 256, 256>>>(keys, pek, kin, TKV);

    // h2 = relu(inputs @ w_first + b_first)
    gemm_kernel<A_NORMAL, false, E_RELU><<<gemm_grid(M, EMBED, 1), 256>>>(
        inputs, w_first, h2, b_first, nullptr,
        M, EMBED, NMELS_R, 0, 0, 0, 0, 0.0f);
    // fc0: h2 -> h ; fc1: h -> h2 ; fc2: h2 -> h
    gemm_kernel<A_NORMAL, false, E_RELU><<<gemm_grid(M, EMBED, 1), 256>>>(
        h2, fc_w + 0 * EMBED * EMBED, h, fc_b + 0 * EMBED, nullptr,
        M, EMBED, EMBED, 0, 0, 0, 0, 0.0f);
    gemm_kernel<A_NORMAL, false, E_RELU><<<gemm_grid(M, EMBED, 1), 256>>>(
        h, fc_w + 1 * EMBED * EMBED, h2, fc_b + 1 * EMBED, nullptr,
        M, EMBED, EMBED, 0, 0, 0, 0, 0.0f);
    gemm_kernel<A_NORMAL, false, E_RELU><<<gemm_grid(M, EMBED, 1), 256>>>(
        h2, fc_w + 2 * EMBED * EMBED, h, fc_b + 2 * EMBED, nullptr,
        M, EMBED, EMBED, 0, 0, 0, 0, 0.0f);

    for (int i = 0; i < NLAYERS; i++) {
        const int dil = 1 << i;
        // conv (im2col gather GEMM): big[M,512] = conv(h) + bias
        gemm_kernel<A_CONV, false, E_BIAS><<<gemm_grid(M, 512, 1), 256>>>(
            h, conv_w + (long long)i * 5 * EMBED * 512, big,
            conv_b + i * 512, nullptr,
            M, 512, 5 * EMBED, 0, 0, 0, dil, 0.0f);
        // GLU + residual into h; qin = h + peq fused
        glu_kernel<<<(M * EMBED + 255) / 256, 256>>>(big, h, qin, peq);

        // q/k/v projections
        gemm_kernel<A_NORMAL, false, E_BIAS><<<gemm_grid(M, EMBED, 1), 256>>>(
            qin, att_w2 + (long long)i * EMBED * EMBED, h2,
            att_b2 + i * EMBED, nullptr,
            M, EMBED, EMBED, 0, 0, 0, 0, 0.0f);
        gemm_kernel<A_NORMAL, false, E_BIAS><<<gemm_grid(Mk, EMBED, 1), 256>>>(
            kin, att_w1 + (long long)i * EMBED * EMBED, kout,
            att_b1 + i * EMBED, nullptr,
            Mk, EMBED, EMBED, 0, 0, 0, 0, 0.0f);
        gemm_kernel<A_NORMAL, false, E_BIAS><<<gemm_grid(Mk, EMBED, 1), 256>>>(
            values, att_w3 + (long long)i * EMBED * EMBED, vout,
            att_b3 + i * EMBED, nullptr,
            Mk, EMBED, EMBED, 0, 0, 0, 0, 0.0f);

        // scores[b] = qout[b] @ kout[b]^T   (batched, TRANSB)
        gemm_kernel<A_NORMAL, true, E_NONE><<<gemm_grid(TQ, TKV, BATCH), 256>>>(
            h2, kout, big, nullptr, nullptr,
            TQ, TKV, EMBED,
            (long long)TQ * EMBED, (long long)TKV * EMBED, (long long)TQ * TKV,
            0, 0.0f);
        // softmax over keys
        softmax_kernel<<<M, 128>>>(big);
        // ctx[b] = softmax @ vout[b] * rsqrt(TK)
        gemm_kernel<A_NORMAL, false, E_SCALE><<<gemm_grid(TQ, EMBED, BATCH), 256>>>(
            big, vout, ctx, nullptr, nullptr,
            TQ, EMBED, TKV,
            (long long)TQ * TKV, (long long)TKV * EMBED, (long long)TQ * EMBED,
            0, rsqrt_tk);
        // h = (ctx @ wo + bo + h) * sqrt(0.5)
        gemm_kernel<A_NORMAL, false, E_RESID><<<gemm_grid(M, EMBED, 1), 256>>>(
            ctx, att_wo + (long long)i * EMBED * EMBED, h,
            att_bo + i * EMBED, h,
            M, EMBED, EMBED, 0, 0, 0, 0, 0.0f);
    }

    // mel head
    gemm_kernel<A_NORMAL, false, E_BIAS><<<gemm_grid(M, NMELS_R, 1), 256>>>(
        h, w_mel, out_mel, b_mel, nullptr,
        M, NMELS_R, EMBED, 0, 0, 0, 0, 0.0f);
    // done head
    done_kernel<<<(M + 7) / 8, 256>>>(h, w_done, b_done, out_done);
    // h output
    cudaMemcpyAsync(out_h, h, sizeof(float) * (size_t)M * EMBED,
                    cudaMemcpyDeviceToDevice);
}

// round 7
// speedup vs baseline: 1.6542x; 1.4135x over previous
#include <cuda_runtime.h>
#include <math.h>
#include <stdint.h>

#define EMBED 256
#define BATCH 32
#define TQ 1024
#define TKV 512
#define NMELS_R 320
#define NLAYERS 4
#define SQRT_HALF 0.70710678118654752440f
#define KTILE 16

// ---------------- scratch (device globals; no allocation allowed) ----------------
__device__ float g_h   [BATCH * TQ * EMBED];
__device__ float g_h2  [BATCH * TQ * EMBED];
__device__ float g_ctx [BATCH * TQ * EMBED];
__device__ float g_qin [BATCH * TQ * EMBED];
__device__ float g_kin [BATCH * TKV * EMBED];
__device__ float g_kout[BATCH * TKV * EMBED];
__device__ float g_vout[BATCH * TKV * EMBED];
__device__ float g_big [BATCH * TQ * 512];
__device__ float g_peq [TQ * EMBED];
__device__ float g_pek [TKV * EMBED];

// ---------------- cp.async helpers ----------------
__device__ __forceinline__ uint32_t smem_u32(const void* p) {
    return (uint32_t)__cvta_generic_to_shared(p);
}
__device__ __forceinline__ void cp_async16(uint32_t dst, const void* src, int src_bytes) {
    asm volatile("cp.async.cg.shared.global [%0], [%1], 16, %2;\n"
                 :: "r"(dst), "l"(src), "r"(src_bytes));
}
__device__ __forceinline__ void cp_async_commit() {
    asm volatile("cp.async.commit_group;\n");
}
__device__ __forceinline__ void cp_async_wait0() {
    asm volatile("cp.async.wait_group 0;\n");
}

// ---------------- 3xTF32 split helpers ----------------
// x = hi + lo with hi, lo tf32-representable; hi*hi + lo*hi + hi*lo in fp32
// accumulators recovers ~21 mantissa bits => per-GEMM rel err ~1e-7 (fp32-equivalent).
__device__ __forceinline__ void split_tf32(float x, uint32_t& hi, uint32_t& lo) {
    float h, l;
    asm("cvt.rna.tf32.f32 %0, %1;" : "=f"(h) : "f"(x));
    float d = x - h;
    asm("cvt.rna.tf32.f32 %0, %1;" : "=f"(l) : "f"(d));
    hi = __float_as_uint(h);
    lo = __float_as_uint(l);
}
__device__ __forceinline__ void mma_tf32(float* c, const uint32_t* a, const uint32_t* b) {
    asm volatile(
        "mma.sync.aligned.m16n8k8.row.col.f32.tf32.tf32.f32 "
        "{%0,%1,%2,%3}, {%4,%5,%6,%7}, {%8,%9}, {%0,%1,%2,%3};"
        : "+f"(c[0]), "+f"(c[1]), "+f"(c[2]), "+f"(c[3])
        : "r"(a[0]), "r"(a[1]), "r"(a[2]), "r"(a[3]), "r"(b[0]), "r"(b[1]));
}

// ---------------- positional encoding (VERIFIED R5 @5.5e-7 — DO NOT CHANGE) ----------------
__global__ void posenc_kernel(float* __restrict__ pe, int T, float rate) {
    int idx = blockIdx.x * blockDim.x + threadIdx.x;
    if (idx >= T * EMBED) return;
    int t = idx / EMBED;
    int c = idx - t * EMBED;
    double e = (double)(2.0f * (float)(c >> 1) / 256.0f);
    float power = (float)pow(10000.0, e);
    float recip = 1.0f / power;
    float p  = (float)t;
    float t1 = p * rate;
    float t2 = t1 * recip;
    float angle = p * t2;
    double a = (double)angle;
    pe[idx] = (c & 1) ? (float)cos(a) : (float)sin(a);
}

// ---------------- kin = keys + pek ----------------
__global__ void addpe_kernel(const float* __restrict__ x, const float* __restrict__ pe,
                             float* __restrict__ y, int period) {
    long long idx = (long long)blockIdx.x * blockDim.x + threadIdx.x;
    long long r = idx >> 8;
    int c = (int)(idx & 255);
    int t = (int)(r & (period - 1));
    y[idx] = x[idx] + pe[t * EMBED + c];
}

// ---------------- TF32 tensor-core GEMM, double-buffered cp.async ----------------
enum AMode { A_NORMAL = 0, A_CONV = 2 };
enum Epi   { E_RELU = 0, E_BIAS = 1, E_NONE = 2, E_SCALE = 3, E_RESID = 4 };

// C[M,N] = epi( A[M,K] @ B[K,N] );  TRANSB: B stored [N,K].
// 128x128x16 CTA tile, 8 warps (2x4), warp tile 64x32 via 4x4 m16n8k8 mma.
// A_CONV: row r -> (b=r>>10, t=r&1023); k = tap*256+ci gathers h[b, t-(4-tap)*dil, ci].
// Requirements: M%128==0, K%16==0, N%2==0.
template<int AMODE, bool TRANSB, int EPI>
__global__ void __launch_bounds__(256, 1)
gemm_kernel(const float* __restrict__ A, const float* __restrict__ Bm,
            float* __restrict__ C,
            const float* __restrict__ bias,
            const float* __restrict__ resid,
            int M, int N, int K,
            long long sA, long long sB, long long sC,
            int dil, float scale)
{
    // Padded strides chosen for conflict-free mma-fragment LDS:
    // A row stride 20 words: bank = (20g + t) mod 32 distinct for g<8,t<4.
    // B row stride 136 words: bank = (8t + g) mod 32 distinct.
    __shared__ float As[2][128][20];
    __shared__ float Bs[2][KTILE][136];

    const int bz = blockIdx.z;
    A  += bz * sA;
    Bm += bz * sB;
    C  += bz * sC;

    const int row0 = blockIdx.y * 128;
    const int col0 = blockIdx.x * 128;
    const int tid  = threadIdx.x;
    const int lane = tid & 31;
    const int warp = tid >> 5;
    const int wm = warp >> 2;          // 0..1
    const int wn = warp & 3;           // 0..3
    const int m0 = wm * 64;
    const int n0 = wn * 32;
    const int g = lane >> 2;           // 0..7
    const int t = lane & 3;            // 0..3

    const int nk = K / KTILE;

    // ---- tile loaders ----
    auto load_A = [&](int kt, int b) {
#pragma unroll
        for (int u = 0; u < 2; u++) {
            const int idx = tid + u * 256;
            const int r  = idx >> 2;
            const int kc = (idx & 3) * 4;
            const int gr = row0 + r;
            const int kg = kt * KTILE + kc;
            const float* src;
            int sz = 16;
            if (AMODE == A_CONV) {
                const int tap = kg >> 8;
                const int ci  = kg & 255;
                const int shift = (4 - tap) * dil;
                const int b_ = gr >> 10;
                const int t_ = gr & 1023;
                if (t_ >= shift)
                    src = A + ((long long)((b_ << 10) + (t_ - shift))) * EMBED + ci;
                else { src = A; sz = 0; }
            } else {
                src = A + (long long)gr * K + kg;
            }
            cp_async16(smem_u32(&As[b][r][kc]), src, sz);
        }
    };
    auto load_B = [&](int kt, int b) {
#pragma unroll
        for (int u = 0; u < 2; u++) {
            const int idx = tid + u * 256;
            const int kk = idx >> 5;
            const int nc = (idx & 31) * 4;
            const int gn = col0 + nc;
            const float* src = Bm + (long long)(kt * KTILE + kk) * N + gn;
            int sz = (gn < N) ? 16 : 0;
            if (gn >= N) src = Bm;
            cp_async16(smem_u32(&Bs[b][kk][nc]), src, sz);
        }
    };
    float4 tb[2];
    auto ldg_Bt = [&](int kt) {
#pragma unroll
        for (int u = 0; u < 2; u++) {
            const int idx = tid + u * 256;
            const int n  = idx >> 2;
            const int kc = (idx & 3) * 4;
            const int gn = col0 + n;
            tb[u] = (gn < N) ? *(const float4*)&Bm[(long long)gn * K + kt * KTILE + kc]
                             : make_float4(0.f, 0.f, 0.f, 0.f);
        }
    };
    auto sts_Bt = [&](int b) {
#pragma unroll
        for (int u = 0; u < 2; u++) {
            const int idx = tid + u * 256;
            const int n  = idx >> 2;
            const int kc = (idx & 3) * 4;
            Bs[b][kc + 0][n] = tb[u].x;
            Bs[b][kc + 1][n] = tb[u].y;
            Bs[b][kc + 2][n] = tb[u].z;
            Bs[b][kc + 3][n] = tb[u].w;
        }
    };

    float acc[4][4][4];
#pragma unroll
    for (int i = 0; i < 4; i++)
#pragma unroll
        for (int j = 0; j < 4; j++)
#pragma unroll
            for (int r = 0; r < 4; r++) acc[i][j][r] = 0.0f;

    // ---- prologue ----
    load_A(0, 0);
    if (!TRANSB) {
        load_B(0, 0);
        cp_async_commit();
        cp_async_wait0();
    } else {
        cp_async_commit();
        ldg_Bt(0);
        cp_async_wait0();
        sts_Bt(0);
    }
    __syncthreads();

    for (int kt = 0; kt < nk; kt++) {
        const int cur = kt & 1;
        const int nxt = cur ^ 1;
        const bool more = (kt + 1 < nk);

        if (more) {
            load_A(kt + 1, nxt);
            if (!TRANSB) load_B(kt + 1, nxt);
            cp_async_commit();
            if (TRANSB) ldg_Bt(kt + 1);
        }

        // ---- compute on cur: 2 k8 steps ----
#pragma unroll
        for (int step = 0; step < 2; step++) {
            const int kk = step * 8;
            uint32_t ahi[4][4], alo[4][4], bhi[4][2], blo[4][2];
#pragma unroll
            for (int i = 0; i < 4; i++) {
                const int r = m0 + i * 16 + g;
                split_tf32(As[cur][r    ][kk + t    ], ahi[i][0], alo[i][0]);
                split_tf32(As[cur][r + 8][kk + t    ], ahi[i][1], alo[i][1]);
                split_tf32(As[cur][r    ][kk + t + 4], ahi[i][2], alo[i][2]);
                split_tf32(As[cur][r + 8][kk + t + 4], ahi[i][3], alo[i][3]);
            }
#pragma unroll
            for (int j = 0; j < 4; j++) {
                const int n = n0 + j * 8 + g;
                split_tf32(Bs[cur][kk + t    ][n], bhi[j][0], blo[j][0]);
                split_tf32(Bs[cur][kk + t + 4][n], bhi[j][1], blo[j][1]);
            }
#pragma unroll
            for (int i = 0; i < 4; i++)
#pragma unroll
                for (int j = 0; j < 4; j++) {
                    mma_tf32(acc[i][j], ahi[i], bhi[j]);
                    mma_tf32(acc[i][j], alo[i], bhi[j]);
                    mma_tf32(acc[i][j], ahi[i], blo[j]);
                }
        }

        if (more && TRANSB) sts_Bt(nxt);
        cp_async_wait0();
        __syncthreads();
    }

    // ---- epilogue: c0/c1 = (row, col..col+1), c2/c3 = (row+8, col..col+1) ----
#pragma unroll
    for (int i = 0; i < 4; i++) {
#pragma unroll
        for (int j = 0; j < 4; j++) {
            const int cc = col0 + n0 + j * 8 + t * 2;
            if (cc >= N) continue;
#pragma unroll
            for (int half = 0; half < 2; half++) {
                const int r = row0 + m0 + i * 16 + g + half * 8;
                float v0 = acc[i][j][half * 2 + 0];
                float v1 = acc[i][j][half * 2 + 1];
                if (EPI == E_RELU)  { v0 = fmaxf(v0 + bias[cc], 0.0f); v1 = fmaxf(v1 + bias[cc + 1], 0.0f); }
                if (EPI == E_BIAS)  { v0 += bias[cc]; v1 += bias[cc + 1]; }
                if (EPI == E_SCALE) { v0 *= scale; v1 *= scale; }
                if (EPI == E_RESID) {
                    const float2 rs = *(const float2*)&resid[(long long)r * N + cc];
                    v0 = (v0 + bias[cc]     + rs.x) * SQRT_HALF;
                    v1 = (v1 + bias[cc + 1] + rs.y) * SQRT_HALF;
                }
                *(float2*)&C[(long long)r * N + cc] = make_float2(v0, v1);
            }
        }
    }
}

// ---------------- GLU + residual + fused q-input ----------------
__global__ void glu_kernel(const float* __restrict__ y, float* __restrict__ h,
                           float* __restrict__ qin, const float* __restrict__ peq) {
    long long idx = (long long)blockIdx.x * blockDim.x + threadIdx.x;
    if (idx >= (long long)BATCH * TQ * EMBED) return;
    long long r = idx >> 8;
    int c = (int)(idx & 255);
    int t = (int)(r & 1023);
    float a = y[r * 512 + c];
    float g = y[r * 512 + 256 + c];
    float s = 1.0f / (1.0f + expf(-g));
    float hv = (h[idx] + a * s) * SQRT_HALF;
    h[idx] = hv;
    qin[idx] = hv + peq[t * EMBED + c];
}

// ---------------- row softmax over 512 ----------------
__global__ void softmax_kernel(float* __restrict__ x) {
    __shared__ float red[128];
    float* p = x + (long long)blockIdx.x * 512;
    const int tid = threadIdx.x;
    float v[4];
    float m = -1e30f;
#pragma unroll
    for (int i = 0; i < 4; i++) { v[i] = p[tid + i * 128]; m = fmaxf(m, v[i]); }
    red[tid] = m; __syncthreads();
#pragma unroll
    for (int s = 64; s > 0; s >>= 1) {
        if (tid < s) red[tid] = fmaxf(red[tid], red[tid + s]);
        __syncthreads();
    }
    m = red[0];
    __syncthreads();
    float sum = 0.0f;
#pragma unroll
    for (int i = 0; i < 4; i++) { v[i] = expf(v[i] - m); sum += v[i]; }
    red[tid] = sum; __syncthreads();
#pragma unroll
    for (int s = 64; s > 0; s >>= 1) {
        if (tid < s) red[tid] += red[tid + s];
        __syncthreads();
    }
    float inv = 1.0f / red[0];
#pragma unroll
    for (int i = 0; i < 4; i++) p[tid + i * 128] = v[i] * inv;
}

// ---------------- done head ----------------
__global__ void done_kernel(const float* __restrict__ h, const float* __restrict__ w,
                            const float* __restrict__ b, float* __restrict__ out) {
    const int row  = blockIdx.x * 8 + (threadIdx.x >> 5);
    const int lane = threadIdx.x & 31;
    if (row >= BATCH * TQ) return;
    const float* hr = h + (long long)row * EMBED;
    float s0 = 0.0f, s1 = 0.0f;
    for (int k = lane; k < EMBED; k += 32) {
        float hv = hr[k];
        s0 = fmaf(hv, w[k * 2 + 0], s0);
        s1 = fmaf(hv, w[k * 2 + 1], s1);
    }
#pragma unroll
    for (int o = 16; o > 0; o >>= 1) {
        s0 += __shfl_down_sync(0xffffffffu, s0, o);
        s1 += __shfl_down_sync(0xffffffffu, s1, o);
    }
    if (lane == 0) {
        out[row * 2 + 0] = 1.0f / (1.0f + expf(-(s0 + b[0])));
        out[row * 2 + 1] = 1.0f / (1.0f + expf(-(s1 + b[1])));
    }
}

// ---------------- host orchestration ----------------
static inline dim3 gemm_grid(int M, int N, int z) {
    return dim3((N + 127) / 128, (M + 127) / 128, z);
}

extern "C" void kernel_launch(void* const* d_in, const int* in_sizes, int n_in,
                              void* d_out, int out_size) {
    const float* inputs  = (const float*)d_in[0];
    const float* keys    = (const float*)d_in[1];
    const float* values  = (const float*)d_in[2];
    const float* w_first = (const float*)d_in[3];
    const float* b_first = (const float*)d_in[4];
    const float* fc_w    = (const float*)d_in[5];
    const float* fc_b    = (const float*)d_in[6];
    const float* conv_w  = (const float*)d_in[7];
    const float* conv_b  = (const float*)d_in[8];
    const float* att_w1  = (const float*)d_in[9];
    const float* att_b1  = (const float*)d_in[10];
    const float* att_w2  = (const float*)d_in[11];
    const float* att_b2  = (const float*)d_in[12];
    const float* att_w3  = (const float*)d_in[13];
    const float* att_b3  = (const float*)d_in[14];
    const float* att_wo  = (const float*)d_in[15];
    const float* att_bo  = (const float*)d_in[16];
    const float* w_done  = (const float*)d_in[17];
    const float* b_done  = (const float*)d_in[18];
    const float* w_mel   = (const float*)d_in[19];
    const float* b_mel   = (const float*)d_in[20];

    float* out      = (float*)d_out;
    float* out_mel  = out;
    float* out_done = out + (long long)BATCH * TQ * NMELS_R;
    float* out_h    = out_done + (long long)BATCH * TQ * 2;

    float *h, *h2, *ctx, *qin, *kin, *kout, *vout, *big, *peq, *pek;
    cudaGetSymbolAddress((void**)&h,    g_h);
    cudaGetSymbolAddress((void**)&h2,   g_h2);
    cudaGetSymbolAddress((void**)&ctx,  g_ctx);
    cudaGetSymbolAddress((void**)&qin,  g_qin);
    cudaGetSymbolAddress((void**)&kin,  g_kin);
    cudaGetSymbolAddress((void**)&kout, g_kout);
    cudaGetSymbolAddress((void**)&vout, g_vout);
    cudaGetSymbolAddress((void**)&big,  g_big);
    cudaGetSymbolAddress((void**)&peq,  g_peq);
    cudaGetSymbolAddress((void**)&pek,  g_pek);

    const int M  = BATCH * TQ;    // 32768
    const int Mk = BATCH * TKV;   // 16384
    const float rsqrt_tk = 1.0f / sqrtf((float)TKV);

    posenc_kernel<<<(TQ * EMBED + 255) / 256, 256>>>(peq, TQ, 1.0f);
    posenc_kernel<<<(TKV * EMBED + 255) / 256, 256>>>(pek, TKV, 2.0f);
    addpe_kernel<<<(Mk * EMBED + 255) / 256, 256>>>(keys, pek, kin, TKV);

    gemm_kernel<A_NORMAL, false, E_RELU><<<gemm_grid(M, EMBED, 1), 256>>>(
        inputs, w_first, h2, b_first, nullptr,
        M, EMBED, NMELS_R, 0, 0, 0, 0, 0.0f);
    gemm_kernel<A_NORMAL, false, E_RELU><<<gemm_grid(M, EMBED, 1), 256>>>(
        h2, fc_w + 0 * EMBED * EMBED, h, fc_b + 0 * EMBED, nullptr,
        M, EMBED, EMBED, 0, 0, 0, 0, 0.0f);
    gemm_kernel<A_NORMAL, false, E_RELU><<<gemm_grid(M, EMBED, 1), 256>>>(
        h, fc_w + 1 * EMBED * EMBED, h2, fc_b + 1 * EMBED, nullptr,
        M, EMBED, EMBED, 0, 0, 0, 0, 0.0f);
    gemm_kernel<A_NORMAL, false, E_RELU><<<gemm_grid(M, EMBED, 1), 256>>>(
        h2, fc_w + 2 * EMBED * EMBED, h, fc_b + 2 * EMBED, nullptr,
        M, EMBED, EMBED, 0, 0, 0, 0, 0.0f);

    for (int i = 0; i < NLAYERS; i++) {
        const int dil = 1 << i;
        gemm_kernel<A_CONV, false, E_BIAS><<<gemm_grid(M, 512, 1), 256>>>(
            h, conv_w + (long long)i * 5 * EMBED * 512, big,
            conv_b + i * 512, nullptr,
            M, 512, 5 * EMBED, 0, 0, 0, dil, 0.0f);
        glu_kernel<<<(M * EMBED + 255) / 256, 256>>>(big, h, qin, peq);

        gemm_kernel<A_NORMAL, false, E_BIAS><<<gemm_grid(M, EMBED, 1), 256>>>(
            qin, att_w2 + (long long)i * EMBED * EMBED, h2,
            att_b2 + i * EMBED, nullptr,
            M, EMBED, EMBED, 0, 0, 0, 0, 0.0f);
        gemm_kernel<A_NORMAL, false, E_BIAS><<<gemm_grid(Mk, EMBED, 1), 256>>>(
            kin, att_w1 + (long long)i * EMBED * EMBED, kout,
            att_b1 + i * EMBED, nullptr,
            Mk, EMBED, EMBED, 0, 0, 0, 0, 0.0f);
        gemm_kernel<A_NORMAL, false, E_BIAS><<<gemm_grid(Mk, EMBED, 1), 256>>>(
            values, att_w3 + (long long)i * EMBED * EMBED, vout,
            att_b3 + i * EMBED, nullptr,
            Mk, EMBED, EMBED, 0, 0, 0, 0, 0.0f);

        gemm_kernel<A_NORMAL, true, E_NONE><<<gemm_grid(TQ, TKV, BATCH), 256>>>(
            h2, kout, big, nullptr, nullptr,
            TQ, TKV, EMBED,
            (long long)TQ * EMBED, (long long)TKV * EMBED, (long long)TQ * TKV,
            0, 0.0f);
        softmax_kernel<<<M, 128>>>(big);
        gemm_kernel<A_NORMAL, false, E_SCALE><<<gemm_grid(TQ, EMBED, BATCH), 256>>>(
            big, vout, ctx, nullptr, nullptr,
            TQ, EMBED, TKV,
            (long long)TQ * TKV, (long long)TKV * EMBED, (long long)TQ * EMBED,
            0, rsqrt_tk);
        gemm_kernel<A_NORMAL, false, E_RESID><<<gemm_grid(M, EMBED, 1), 256>>>(
            ctx, att_wo + (long long)i * EMBED * EMBED, h,
            att_bo + i * EMBED, h,
            M, EMBED, EMBED, 0, 0, 0, 0, 0.0f);
    }

    gemm_kernel<A_NORMAL, false, E_BIAS><<<gemm_grid(M, NMELS_R, 1), 256>>>(
        h, w_mel, out_mel, b_mel, nullptr,
        M, NMELS_R, EMBED, 0, 0, 0, 0, 0.0f);
    done_kernel<<<(M + 7) / 8, 256>>>(h, w_done, b_done, out_done);
    cudaMemcpyAsync(out_h, h, sizeof(float) * (size_t)M * EMBED,
                    cudaMemcpyDeviceToDevice);
}